// round 1
// baseline (speedup 1.0000x reference)
#include <cuda_runtime.h>
#include <cuda_bf16.h>
#include <math.h>

#define NN_MAX 50000
#define EE_MAX 1600000
#define DIMF 128
#define BM 64
#define WT_STRIDE 132
#define XS_STRIDE 65

// -------- scratch (static device globals; no allocation allowed) --------
__device__ float g_z[NN_MAX * DIMF];
__device__ float g_h[NN_MAX * DIMF];
__device__ float g_asrc[NN_MAX];
__device__ float g_adst[NN_MAX];
__device__ int   g_menc[NN_MAX];
__device__ float g_s[NN_MAX];
__device__ int   g_deg[NN_MAX];
__device__ int   g_off[NN_MAX + 1];
__device__ int   g_cur[NN_MAX];
__device__ int   g_csrc[EE_MAX];

// monotonic float<->int encoding for atomicMax over signed int
__device__ __forceinline__ int fenc(float f) {
    int i = __float_as_int(f);
    return (i >= 0) ? i : (i ^ 0x7fffffff);
}
__device__ __forceinline__ float fdec(int i) {
    return __int_as_float((i >= 0) ? i : (i ^ 0x7fffffff));
}

// ======================= GEMM + attention logits =======================
// z[m][n] = sum_k x[m][k]*W[n][k] + b[n]
// asrc[m] = z[m]·aW[0:128], adst[m] = z[m]·aW[128:256]
__global__ void gemm_attn_kernel(const float* __restrict__ x,
                                 const float* __restrict__ W,
                                 const float* __restrict__ b,
                                 const float* __restrict__ aW,
                                 float* __restrict__ z,
                                 float* __restrict__ asrc,
                                 float* __restrict__ adst,
                                 int n)
{
    extern __shared__ float sh[];
    float* wt = sh;                         // [128][WT_STRIDE]  W transposed: wt[k][n]
    float* xs = sh + DIMF * WT_STRIDE;      // [128][XS_STRIDE]  x transposed: xs[k][m]
    const int tid = threadIdx.x;
    const int m0 = blockIdx.x * BM;

    // load W transposed (coalesced global reads)
    for (int i = tid; i < DIMF * DIMF; i += 256) {
        int nn = i >> 7, kk = i & 127;
        wt[kk * WT_STRIDE + nn] = W[i];
    }
    // load x tile transposed (coalesced global reads)
    for (int i = tid; i < BM * DIMF; i += 256) {
        int mm = i >> 7, kk = i & 127;
        int gm = m0 + mm;
        xs[kk * XS_STRIDE + mm] = (gm < n) ? x[(size_t)gm * DIMF + kk] : 0.f;
    }
    __syncthreads();

    const int w  = tid >> 5;   // warp id 0..7 -> rows m0 + w*8 .. +7
    const int ln = tid & 31;   // lane -> columns ln*4 .. ln*4+3

    float c[8][4];
#pragma unroll
    for (int i = 0; i < 8; i++) { c[i][0] = c[i][1] = c[i][2] = c[i][3] = 0.f; }

    const float* xw = xs + w * 8;
#pragma unroll 2
    for (int k = 0; k < DIMF; k++) {
        float4 wv = *(const float4*)(wt + k * WT_STRIDE + ln * 4);
        const float* xk = xw + k * XS_STRIDE;
#pragma unroll
        for (int i = 0; i < 8; i++) {
            float xv = xk[i];
            c[i][0] += xv * wv.x;
            c[i][1] += xv * wv.y;
            c[i][2] += xv * wv.z;
            c[i][3] += xv * wv.w;
        }
    }

    float4 bv = *(const float4*)(b + ln * 4);
    float4 lo = *(const float4*)(aW + ln * 4);
    float4 hi = *(const float4*)(aW + DIMF + ln * 4);

#pragma unroll
    for (int i = 0; i < 8; i++) {
        int m = m0 + w * 8 + i;
        float4 zv;
        zv.x = c[i][0] + bv.x;
        zv.y = c[i][1] + bv.y;
        zv.z = c[i][2] + bv.z;
        zv.w = c[i][3] + bv.w;
        float ps = zv.x * lo.x + zv.y * lo.y + zv.z * lo.z + zv.w * lo.w;
        float pd = zv.x * hi.x + zv.y * hi.y + zv.z * hi.z + zv.w * hi.w;
#pragma unroll
        for (int o = 16; o > 0; o >>= 1) {
            ps += __shfl_xor_sync(0xffffffffu, ps, o);
            pd += __shfl_xor_sync(0xffffffffu, pd, o);
        }
        if (m < n) {
            *(float4*)(z + (size_t)m * DIMF + ln * 4) = zv;
            if (ln == 0) { asrc[m] = ps; adst[m] = pd; }
        }
    }
}

// ======================= CSR build =======================
__global__ void zero_deg_kernel(int* deg, int n) {
    int i = blockIdx.x * blockDim.x + threadIdx.x;
    if (i < n) deg[i] = 0;
}
__global__ void hist_kernel(const int* __restrict__ dst, int* deg, int e) {
    int i = blockIdx.x * blockDim.x + threadIdx.x;
    if (i < e) atomicAdd(&deg[dst[i]], 1);
}
__global__ void scan_kernel(const int* __restrict__ deg, int* off, int n) {
    __shared__ int sh[1024];
    __shared__ int carry;
    int tid = threadIdx.x;
    if (tid == 0) { carry = 0; off[0] = 0; }
    __syncthreads();
    for (int base = 0; base < n; base += 1024) {
        int idx = base + tid;
        int v = (idx < n) ? deg[idx] : 0;
        sh[tid] = v;
        __syncthreads();
        for (int d = 1; d < 1024; d <<= 1) {
            int t = (tid >= d) ? sh[tid - d] : 0;
            __syncthreads();
            sh[tid] += t;
            __syncthreads();
        }
        int incl = sh[tid] + carry;
        if (idx < n) off[idx + 1] = incl;
        __syncthreads();
        if (tid == 1023) carry = incl;
        __syncthreads();
    }
}
__global__ void copy_cur_kernel(const int* __restrict__ off, int* cur, int n) {
    int i = blockIdx.x * blockDim.x + threadIdx.x;
    if (i < n) cur[i] = off[i];
}
__global__ void scatter_kernel(const int* __restrict__ src, const int* __restrict__ dst,
                               int* cur, int* csrc, int e) {
    int i = blockIdx.x * blockDim.x + threadIdx.x;
    if (i < e) {
        int pos = atomicAdd(&cur[dst[i]], 1);
        csrc[pos] = src[i];
    }
}

// ======================= softmax (edge-parallel) =======================
__global__ void init_ms_kernel(int* menc, float* s, int n) {
    int i = blockIdx.x * blockDim.x + threadIdx.x;
    if (i < n) { menc[i] = (int)0x80000000; s[i] = 0.f; }
}
__global__ void edge_max_kernel(const int* __restrict__ src, const int* __restrict__ dst,
                                const float* __restrict__ asrc, const float* __restrict__ adst,
                                const float* __restrict__ ab, int* menc, int e) {
    int i = blockIdx.x * blockDim.x + threadIdx.x;
    if (i >= e) return;
    int si = src[i], d = dst[i];
    float ev = asrc[si] + adst[d] + ab[0];
    ev = ev > 0.f ? ev : 0.01f * ev;
    atomicMax(&menc[d], fenc(ev));
}
__global__ void edge_sum_kernel(const int* __restrict__ src, const int* __restrict__ dst,
                                const float* __restrict__ asrc, const float* __restrict__ adst,
                                const float* __restrict__ ab, const int* __restrict__ menc,
                                float* s, int e) {
    int i = blockIdx.x * blockDim.x + threadIdx.x;
    if (i >= e) return;
    int si = src[i], d = dst[i];
    float ev = asrc[si] + adst[d] + ab[0];
    ev = ev > 0.f ? ev : 0.01f * ev;
    float mv = fdec(menc[d]);
    atomicAdd(&s[d], expf(ev - mv));
}

// ======================= aggregation: warp per dst node =======================
__global__ void aggregate_kernel(const int* __restrict__ off, const int* __restrict__ csrc,
                                 const float* __restrict__ asrc, const float* __restrict__ adst,
                                 const float* __restrict__ ab, const int* __restrict__ menc,
                                 const float* __restrict__ s, const float* __restrict__ z,
                                 float* __restrict__ out, int n, int do_relu)
{
    int gw = (blockIdx.x * blockDim.x + threadIdx.x) >> 5;
    int ln = threadIdx.x & 31;
    if (gw >= n) return;
    int beg = off[gw], end = off[gw + 1];
    float dterm = adst[gw] + ab[0];
    float mv = fdec(menc[gw]);
    float sv = s[gw];
    float sinv = (sv > 0.f) ? (1.f / sv) : 0.f;

    float4 acc = make_float4(0.f, 0.f, 0.f, 0.f);
    int j = beg;
    for (; j + 2 <= end; j += 2) {
        int s0 = csrc[j];
        int s1 = csrc[j + 1];
        float4 z0 = *(const float4*)(z + (size_t)s0 * DIMF + ln * 4);
        float4 z1 = *(const float4*)(z + (size_t)s1 * DIMF + ln * 4);
        float a0 = asrc[s0];
        float a1 = asrc[s1];
        float e0 = a0 + dterm; e0 = e0 > 0.f ? e0 : 0.01f * e0;
        float e1 = a1 + dterm; e1 = e1 > 0.f ? e1 : 0.01f * e1;
        float w0 = expf(e0 - mv) * sinv;
        float w1 = expf(e1 - mv) * sinv;
        acc.x += w0 * z0.x + w1 * z1.x;
        acc.y += w0 * z0.y + w1 * z1.y;
        acc.z += w0 * z0.z + w1 * z1.z;
        acc.w += w0 * z0.w + w1 * z1.w;
    }
    if (j < end) {
        int s0 = csrc[j];
        float4 z0 = *(const float4*)(z + (size_t)s0 * DIMF + ln * 4);
        float e0 = asrc[s0] + dterm; e0 = e0 > 0.f ? e0 : 0.01f * e0;
        float w0 = expf(e0 - mv) * sinv;
        acc.x += w0 * z0.x;
        acc.y += w0 * z0.y;
        acc.z += w0 * z0.z;
        acc.w += w0 * z0.w;
    }
    if (do_relu) {
        acc.x = fmaxf(acc.x, 0.f);
        acc.y = fmaxf(acc.y, 0.f);
        acc.z = fmaxf(acc.z, 0.f);
        acc.w = fmaxf(acc.w, 0.f);
    }
    *(float4*)(out + (size_t)gw * DIMF + ln * 4) = acc;
}

// ======================= host launcher =======================
extern "C" void kernel_launch(void* const* d_in, const int* in_sizes, int n_in,
                              void* d_out, int out_size)
{
    const float* x   = (const float*)d_in[0];
    const int*   src = (const int*)d_in[1];
    const int*   dst = (const int*)d_in[2];
    // d_in[3] = t (unused)
    const float* Wp[3]  = { (const float*)d_in[4],  (const float*)d_in[8],  (const float*)d_in[12] };
    const float* bp[3]  = { (const float*)d_in[5],  (const float*)d_in[9],  (const float*)d_in[13] };
    const float* aWp[3] = { (const float*)d_in[6],  (const float*)d_in[10], (const float*)d_in[14] };
    const float* abp[3] = { (const float*)d_in[7],  (const float*)d_in[11], (const float*)d_in[15] };

    const int n = in_sizes[0] / DIMF;
    const int e = in_sizes[1];
    if (n > NN_MAX || e > EE_MAX) return;

    float *z, *h, *as, *ad, *sv;
    int *menc, *deg, *off, *cur, *csrc;
    cudaGetSymbolAddress((void**)&z,    g_z);
    cudaGetSymbolAddress((void**)&h,    g_h);
    cudaGetSymbolAddress((void**)&as,   g_asrc);
    cudaGetSymbolAddress((void**)&ad,   g_adst);
    cudaGetSymbolAddress((void**)&sv,   g_s);
    cudaGetSymbolAddress((void**)&menc, g_menc);
    cudaGetSymbolAddress((void**)&deg,  g_deg);
    cudaGetSymbolAddress((void**)&off,  g_off);
    cudaGetSymbolAddress((void**)&cur,  g_cur);
    cudaGetSymbolAddress((void**)&csrc, g_csrc);

    const int smem_bytes = (DIMF * WT_STRIDE + DIMF * XS_STRIDE) * (int)sizeof(float);
    cudaFuncSetAttribute(gemm_attn_kernel,
                         cudaFuncAttributeMaxDynamicSharedMemorySize, smem_bytes);

    const int TB = 256;
    const int gb_n = (n + TB - 1) / TB;
    const int gb_e = (e + TB - 1) / TB;

    // ---- CSR build (once; shared by all 3 layers) ----
    zero_deg_kernel<<<gb_n, TB>>>(deg, n);
    hist_kernel<<<gb_e, TB>>>(dst, deg, e);
    scan_kernel<<<1, 1024>>>(deg, off, n);
    copy_cur_kernel<<<gb_n, TB>>>(off, cur, n);
    scatter_kernel<<<gb_e, TB>>>(src, dst, cur, csrc, e);

    const float* in = x;
    for (int l = 0; l < 3; l++) {
        gemm_attn_kernel<<<(n + BM - 1) / BM, 256, smem_bytes>>>(
            in, Wp[l], bp[l], aWp[l], z, as, ad, n);
        init_ms_kernel<<<gb_n, TB>>>(menc, sv, n);
        edge_max_kernel<<<gb_e, TB>>>(src, dst, as, ad, abp[l], menc, e);
        edge_sum_kernel<<<gb_e, TB>>>(src, dst, as, ad, abp[l], menc, sv, e);
        float* outp = (l == 2) ? (float*)d_out : h;
        aggregate_kernel<<<(n * 32 + TB - 1) / TB, TB>>>(
            off, csrc, as, ad, abp[l], menc, sv, z, outp, n, (l < 2) ? 1 : 0);
        in = h;
    }
}

// round 2
// speedup vs baseline: 1.2775x; 1.2775x over previous
#include <cuda_runtime.h>
#include <cuda_bf16.h>
#include <math.h>

#define NN_MAX 50000
#define EE_MAX 1600000
#define DIMF 128
#define BM 64
#define TSTRIDE 132   // shared row stride (floats) for both W and x tiles

// -------- scratch (static device globals; no allocation allowed) --------
__device__ float g_z[NN_MAX * DIMF];
__device__ float g_h[NN_MAX * DIMF];
__device__ float g_asrc[NN_MAX];
__device__ float g_adst[NN_MAX];
__device__ int   g_deg[NN_MAX];
__device__ int   g_off[NN_MAX + 1];
__device__ int   g_cur[NN_MAX];
__device__ int   g_csrc[EE_MAX];

// ======================= GEMM + attention logits =======================
// z[m][n] = sum_k x[m][k]*W[n][k] + b[n]
// asrc[m] = z[m]·aW[0:128], adst[m] = z[m]·aW[128:256]
__global__ void gemm_attn_kernel(const float* __restrict__ x,
                                 const float* __restrict__ W,
                                 const float* __restrict__ b,
                                 const float* __restrict__ aW,
                                 float* __restrict__ z,
                                 float* __restrict__ asrc,
                                 float* __restrict__ adst,
                                 int n)
{
    extern __shared__ float sh[];
    float* wt = sh;                      // [128][TSTRIDE]  W transposed: wt[k][n]
    float* xs = sh + DIMF * TSTRIDE;     // [64][TSTRIDE]   x tile row-major: xs[m][k]
    const int tid = threadIdx.x;
    const int m0 = blockIdx.x * BM;

    // load W transposed (coalesced global reads; smem stride 132 keeps LDS.128 conflict-free)
    for (int i = tid; i < DIMF * DIMF; i += 256) {
        int nn = i >> 7, kk = i & 127;
        wt[kk * TSTRIDE + nn] = W[i];
    }
    // load x tile row-major (coalesced global reads, conflict-free contiguous stores)
    for (int i = tid; i < BM * DIMF; i += 256) {
        int mm = i >> 7, kk = i & 127;
        int gm = m0 + mm;
        xs[mm * TSTRIDE + kk] = (gm < n) ? x[(size_t)gm * DIMF + kk] : 0.f;
    }
    __syncthreads();

    const int w  = tid >> 5;   // warp id 0..7 -> rows m0 + w*8 .. +7
    const int ln = tid & 31;   // lane -> columns ln*4 .. ln*4+3

    float c[8][4];
#pragma unroll
    for (int i = 0; i < 8; i++) { c[i][0] = c[i][1] = c[i][2] = c[i][3] = 0.f; }

    const float* xrow = xs + (w * 8) * TSTRIDE;
#pragma unroll 2
    for (int k = 0; k < DIMF; k += 4) {
        float4 w0 = *(const float4*)(wt + (k + 0) * TSTRIDE + ln * 4);
        float4 w1 = *(const float4*)(wt + (k + 1) * TSTRIDE + ln * 4);
        float4 w2 = *(const float4*)(wt + (k + 2) * TSTRIDE + ln * 4);
        float4 w3 = *(const float4*)(wt + (k + 3) * TSTRIDE + ln * 4);
#pragma unroll
        for (int i = 0; i < 8; i++) {
            float4 xv = *(const float4*)(xrow + i * TSTRIDE + k);
            c[i][0] += xv.x * w0.x + xv.y * w1.x + xv.z * w2.x + xv.w * w3.x;
            c[i][1] += xv.x * w0.y + xv.y * w1.y + xv.z * w2.y + xv.w * w3.y;
            c[i][2] += xv.x * w0.z + xv.y * w1.z + xv.z * w2.z + xv.w * w3.z;
            c[i][3] += xv.x * w0.w + xv.y * w1.w + xv.z * w2.w + xv.w * w3.w;
        }
    }

    float4 bv = *(const float4*)(b + ln * 4);
    float4 lo = *(const float4*)(aW + ln * 4);
    float4 hi = *(const float4*)(aW + DIMF + ln * 4);

#pragma unroll
    for (int i = 0; i < 8; i++) {
        int m = m0 + w * 8 + i;
        float4 zv;
        zv.x = c[i][0] + bv.x;
        zv.y = c[i][1] + bv.y;
        zv.z = c[i][2] + bv.z;
        zv.w = c[i][3] + bv.w;
        float ps = zv.x * lo.x + zv.y * lo.y + zv.z * lo.z + zv.w * lo.w;
        float pd = zv.x * hi.x + zv.y * hi.y + zv.z * hi.z + zv.w * hi.w;
#pragma unroll
        for (int o = 16; o > 0; o >>= 1) {
            ps += __shfl_xor_sync(0xffffffffu, ps, o);
            pd += __shfl_xor_sync(0xffffffffu, pd, o);
        }
        if (m < n) {
            *(float4*)(z + (size_t)m * DIMF + ln * 4) = zv;
            if (ln == 0) { asrc[m] = ps; adst[m] = pd; }
        }
    }
}

// ======================= CSR build =======================
__global__ void hist_kernel(const int* __restrict__ dst, int* deg, int e) {
    int i = blockIdx.x * blockDim.x + threadIdx.x;
    if (i < e) atomicAdd(&deg[dst[i]], 1);
}

// single-block scan with warp shuffles; writes off (exclusive+1) and cur (=off[i])
__global__ void scan_kernel(const int* __restrict__ deg, int* off, int* cur, int n) {
    __shared__ int wsum[32];
    __shared__ int carry;
    const int tid = threadIdx.x;
    const int lane = tid & 31;
    const int wid = tid >> 5;
    if (tid == 0) { carry = 0; off[0] = 0; }
    __syncthreads();
    for (int base = 0; base < n; base += 1024) {
        int idx = base + tid;
        int v = (idx < n) ? deg[idx] : 0;
        int x = v;
#pragma unroll
        for (int d = 1; d < 32; d <<= 1) {
            int t = __shfl_up_sync(0xffffffffu, x, d);
            if (lane >= d) x += t;
        }
        if (lane == 31) wsum[wid] = x;
        __syncthreads();
        if (wid == 0) {
            int y = wsum[lane];
#pragma unroll
            for (int d = 1; d < 32; d <<= 1) {
                int t = __shfl_up_sync(0xffffffffu, y, d);
                if (lane >= d) y += t;
            }
            wsum[lane] = y;
        }
        __syncthreads();
        int incl = x + (wid > 0 ? wsum[wid - 1] : 0) + carry;
        if (idx < n) { off[idx + 1] = incl; cur[idx] = incl - v; }
        __syncthreads();
        if (tid == 1023) carry = incl;
        __syncthreads();
    }
}

__global__ void scatter_kernel(const int* __restrict__ src, const int* __restrict__ dst,
                               int* cur, int* csrc, int e) {
    int i = blockIdx.x * blockDim.x + threadIdx.x;
    if (i < e) {
        int pos = atomicAdd(&cur[dst[i]], 1);
        csrc[pos] = src[i];
    }
}

// ============== fused softmax + aggregation: warp per dst node ==============
__global__ void aggregate_kernel(const int* __restrict__ off, const int* __restrict__ csrc,
                                 const float* __restrict__ asrc, const float* __restrict__ adst,
                                 const float* __restrict__ ab,
                                 const float* __restrict__ z,
                                 float* __restrict__ out, int n, int do_relu)
{
    int gw = (blockIdx.x * blockDim.x + threadIdx.x) >> 5;
    int ln = threadIdx.x & 31;
    if (gw >= n) return;
    const int beg = off[gw], end = off[gw + 1];
    const float dterm = adst[gw] + ab[0];

    // pass A: per-lane max of leaky_relu(asrc[s] + dterm)
    float mloc = -3.4e38f;
    for (int j = beg + ln; j < end; j += 32) {
        float ev = asrc[csrc[j]] + dterm;
        ev = ev > 0.f ? ev : 0.01f * ev;
        mloc = fmaxf(mloc, ev);
    }
#pragma unroll
    for (int o = 16; o > 0; o >>= 1)
        mloc = fmaxf(mloc, __shfl_xor_sync(0xffffffffu, mloc, o));
    const float mv = mloc;

    // pass B: per-lane sum of exp(e - mv)
    float sloc = 0.f;
    for (int j = beg + ln; j < end; j += 32) {
        float ev = asrc[csrc[j]] + dterm;
        ev = ev > 0.f ? ev : 0.01f * ev;
        sloc += __expf(0.f) * 0.f + expf(ev - mv);
    }
#pragma unroll
    for (int o = 16; o > 0; o >>= 1)
        sloc += __shfl_xor_sync(0xffffffffu, sloc, o);
    const float sinv = (sloc > 0.f) ? (1.f / sloc) : 0.f;

    // pass C: weighted gather of z rows (all 32 lanes per edge)
    float4 acc = make_float4(0.f, 0.f, 0.f, 0.f);
    int j = beg;
    for (; j + 2 <= end; j += 2) {
        int s0 = csrc[j];
        int s1 = csrc[j + 1];
        float4 z0 = *(const float4*)(z + (size_t)s0 * DIMF + ln * 4);
        float4 z1 = *(const float4*)(z + (size_t)s1 * DIMF + ln * 4);
        float e0 = asrc[s0] + dterm; e0 = e0 > 0.f ? e0 : 0.01f * e0;
        float e1 = asrc[s1] + dterm; e1 = e1 > 0.f ? e1 : 0.01f * e1;
        float w0 = expf(e0 - mv) * sinv;
        float w1 = expf(e1 - mv) * sinv;
        acc.x += w0 * z0.x + w1 * z1.x;
        acc.y += w0 * z0.y + w1 * z1.y;
        acc.z += w0 * z0.z + w1 * z1.z;
        acc.w += w0 * z0.w + w1 * z1.w;
    }
    if (j < end) {
        int s0 = csrc[j];
        float4 z0 = *(const float4*)(z + (size_t)s0 * DIMF + ln * 4);
        float e0 = asrc[s0] + dterm; e0 = e0 > 0.f ? e0 : 0.01f * e0;
        float w0 = expf(e0 - mv) * sinv;
        acc.x += w0 * z0.x;
        acc.y += w0 * z0.y;
        acc.z += w0 * z0.z;
        acc.w += w0 * z0.w;
    }
    if (do_relu) {
        acc.x = fmaxf(acc.x, 0.f);
        acc.y = fmaxf(acc.y, 0.f);
        acc.z = fmaxf(acc.z, 0.f);
        acc.w = fmaxf(acc.w, 0.f);
    }
    *(float4*)(out + (size_t)gw * DIMF + ln * 4) = acc;
}

// ======================= host launcher =======================
extern "C" void kernel_launch(void* const* d_in, const int* in_sizes, int n_in,
                              void* d_out, int out_size)
{
    const float* x   = (const float*)d_in[0];
    const int*   src = (const int*)d_in[1];
    const int*   dst = (const int*)d_in[2];
    // d_in[3] = t (unused)
    const float* Wp[3]  = { (const float*)d_in[4],  (const float*)d_in[8],  (const float*)d_in[12] };
    const float* bp[3]  = { (const float*)d_in[5],  (const float*)d_in[9],  (const float*)d_in[13] };
    const float* aWp[3] = { (const float*)d_in[6],  (const float*)d_in[10], (const float*)d_in[14] };
    const float* abp[3] = { (const float*)d_in[7],  (const float*)d_in[11], (const float*)d_in[15] };

    const int n = in_sizes[0] / DIMF;
    const int e = in_sizes[1];
    if (n > NN_MAX || e > EE_MAX) return;

    float *z, *h, *as, *ad;
    int *deg, *off, *cur, *csrc;
    cudaGetSymbolAddress((void**)&z,    g_z);
    cudaGetSymbolAddress((void**)&h,    g_h);
    cudaGetSymbolAddress((void**)&as,   g_asrc);
    cudaGetSymbolAddress((void**)&ad,   g_adst);
    cudaGetSymbolAddress((void**)&deg,  g_deg);
    cudaGetSymbolAddress((void**)&off,  g_off);
    cudaGetSymbolAddress((void**)&cur,  g_cur);
    cudaGetSymbolAddress((void**)&csrc, g_csrc);

    const int smem_bytes = (DIMF + BM) * TSTRIDE * (int)sizeof(float);
    cudaFuncSetAttribute(gemm_attn_kernel,
                         cudaFuncAttributeMaxDynamicSharedMemorySize, smem_bytes);

    const int TB = 256;
    const int gb_e = (e + TB - 1) / TB;

    // ---- CSR build (shared by all 3 layers) ----
    cudaMemsetAsync(deg, 0, (size_t)n * sizeof(int));
    hist_kernel<<<gb_e, TB>>>(dst, deg, e);
    scan_kernel<<<1, 1024>>>(deg, off, cur, n);
    scatter_kernel<<<gb_e, TB>>>(src, dst, cur, csrc, e);

    const float* in = x;
    for (int l = 0; l < 3; l++) {
        gemm_attn_kernel<<<(n + BM - 1) / BM, 256, smem_bytes>>>(
            in, Wp[l], bp[l], aWp[l], z, as, ad, n);
        float* outp = (l == 2) ? (float*)d_out : h;
        aggregate_kernel<<<(n * 32 + TB - 1) / TB, TB>>>(
            off, csrc, as, ad, abp[l], z, outp, n, (l < 2) ? 1 : 0);
        in = h;
    }
}

// round 3
// speedup vs baseline: 1.3270x; 1.0387x over previous
#include <cuda_runtime.h>
#include <cuda_fp16.h>
#include <math.h>

#define NN_MAX 50000
#define EE_MAX 1600000
#define DIMF 128
#define BM 64
#define WT_STRIDE 132   // padded stride for W tile (16B-aligned rows, staggers STS banks)

// -------- scratch (static device globals; no allocation allowed) --------
__device__ __half g_z[NN_MAX * DIMF];
__device__ float  g_h[NN_MAX * DIMF];
__device__ float  g_asrc[NN_MAX];
__device__ float  g_adst[NN_MAX];
__device__ int    g_deg[NN_MAX];
__device__ int    g_off[NN_MAX + 1];
__device__ int    g_cur[NN_MAX];
__device__ int    g_csrc[EE_MAX];

// ======================= GEMM + attention logits =======================
// z[m][n] = sum_k x[m][k]*W[n][k] + b[n]   (z stored fp16)
// asrc[m] = z[m]·aW[0:128], adst[m] = z[m]·aW[128:256]   (fp32, pre-quantization)
__global__ void __launch_bounds__(512, 2)
gemm_attn_kernel(const float* __restrict__ x,
                 const float* __restrict__ W,
                 const float* __restrict__ b,
                 const float* __restrict__ aW,
                 __half* __restrict__ z,
                 float* __restrict__ asrc,
                 float* __restrict__ adst,
                 int n)
{
    extern __shared__ float sh[];
    float* wt = sh;                         // [128][WT_STRIDE]  W transposed: wt[k][n]
    float* xs = sh + DIMF * WT_STRIDE;      // [64][128]         x tile row-major
    const int tid = threadIdx.x;
    const int m0 = blockIdx.x * BM;

    // load W transposed (coalesced global reads)
    for (int i = tid; i < DIMF * DIMF; i += 512) {
        int nn = i >> 7, kk = i & 127;
        wt[kk * WT_STRIDE + nn] = W[i];
    }
    // load x tile row-major (coalesced; contiguous smem stores)
    for (int i = tid; i < BM * DIMF; i += 512) {
        int mm = i >> 7, kk = i & 127;
        int gm = m0 + mm;
        xs[mm * DIMF + kk] = (gm < n) ? x[(size_t)gm * DIMF + kk] : 0.f;
    }
    __syncthreads();

    const int w  = tid >> 5;   // warp 0..15 -> rows m0 + w*4 .. +3
    const int ln = tid & 31;   // lane -> columns ln*4 .. +3

    float c[4][4];
#pragma unroll
    for (int i = 0; i < 4; i++) { c[i][0] = c[i][1] = c[i][2] = c[i][3] = 0.f; }

    const float* xrow = xs + (w * 4) * DIMF;
#pragma unroll 4
    for (int k = 0; k < DIMF; k += 4) {
        float4 w0 = *(const float4*)(wt + (k + 0) * WT_STRIDE + ln * 4);
        float4 w1 = *(const float4*)(wt + (k + 1) * WT_STRIDE + ln * 4);
        float4 w2 = *(const float4*)(wt + (k + 2) * WT_STRIDE + ln * 4);
        float4 w3 = *(const float4*)(wt + (k + 3) * WT_STRIDE + ln * 4);
#pragma unroll
        for (int i = 0; i < 4; i++) {
            float4 xv = *(const float4*)(xrow + i * DIMF + k);   // broadcast load
            c[i][0] += xv.x * w0.x + xv.y * w1.x + xv.z * w2.x + xv.w * w3.x;
            c[i][1] += xv.x * w0.y + xv.y * w1.y + xv.z * w2.y + xv.w * w3.y;
            c[i][2] += xv.x * w0.z + xv.y * w1.z + xv.z * w2.z + xv.w * w3.z;
            c[i][3] += xv.x * w0.w + xv.y * w1.w + xv.z * w2.w + xv.w * w3.w;
        }
    }

    float4 bv = *(const float4*)(b + ln * 4);
    float4 lo = *(const float4*)(aW + ln * 4);
    float4 hi = *(const float4*)(aW + DIMF + ln * 4);

#pragma unroll
    for (int i = 0; i < 4; i++) {
        int m = m0 + w * 4 + i;
        float4 zv;
        zv.x = c[i][0] + bv.x;
        zv.y = c[i][1] + bv.y;
        zv.z = c[i][2] + bv.z;
        zv.w = c[i][3] + bv.w;
        float ps = zv.x * lo.x + zv.y * lo.y + zv.z * lo.z + zv.w * lo.w;
        float pd = zv.x * hi.x + zv.y * hi.y + zv.z * hi.z + zv.w * hi.w;
#pragma unroll
        for (int o = 16; o > 0; o >>= 1) {
            ps += __shfl_xor_sync(0xffffffffu, ps, o);
            pd += __shfl_xor_sync(0xffffffffu, pd, o);
        }
        if (m < n) {
            __half2 p0 = __floats2half2_rn(zv.x, zv.y);
            __half2 p1 = __floats2half2_rn(zv.z, zv.w);
            uint2 u;
            u.x = *(unsigned*)&p0;
            u.y = *(unsigned*)&p1;
            *(uint2*)(z + (size_t)m * DIMF + ln * 4) = u;
            if (ln == 0) { asrc[m] = ps; adst[m] = pd; }
        }
    }
}

// ======================= CSR build =======================
__global__ void hist_kernel(const int* __restrict__ dst, int* deg, int e) {
    int i = blockIdx.x * blockDim.x + threadIdx.x;
    if (i < e) atomicAdd(&deg[dst[i]], 1);
}

// single-block scan with warp shuffles; writes off (exclusive+1) and cur (=off[i])
__global__ void scan_kernel(const int* __restrict__ deg, int* off, int* cur, int n) {
    __shared__ int wsum[32];
    __shared__ int carry;
    const int tid = threadIdx.x;
    const int lane = tid & 31;
    const int wid = tid >> 5;
    if (tid == 0) { carry = 0; off[0] = 0; }
    __syncthreads();
    for (int base = 0; base < n; base += 1024) {
        int idx = base + tid;
        int v = (idx < n) ? deg[idx] : 0;
        int x = v;
#pragma unroll
        for (int d = 1; d < 32; d <<= 1) {
            int t = __shfl_up_sync(0xffffffffu, x, d);
            if (lane >= d) x += t;
        }
        if (lane == 31) wsum[wid] = x;
        __syncthreads();
        if (wid == 0) {
            int y = wsum[lane];
#pragma unroll
            for (int d = 1; d < 32; d <<= 1) {
                int t = __shfl_up_sync(0xffffffffu, y, d);
                if (lane >= d) y += t;
            }
            wsum[lane] = y;
        }
        __syncthreads();
        int incl = x + (wid > 0 ? wsum[wid - 1] : 0) + carry;
        if (idx < n) { off[idx + 1] = incl; cur[idx] = incl - v; }
        __syncthreads();
        if (tid == 1023) carry = incl;
        __syncthreads();
    }
}

__global__ void scatter_kernel(const int* __restrict__ src, const int* __restrict__ dst,
                               int* cur, int* csrc, int e) {
    int i = blockIdx.x * blockDim.x + threadIdx.x;
    if (i < e) {
        int pos = atomicAdd(&cur[dst[i]], 1);
        csrc[pos] = src[i];
    }
}

// ========= fused softmax + aggregation, SINGLE pass: warp per dst node =========
// h = (sum_j exp(e_j) * z[src_j]) / (sum_j exp(e_j))   -- max-shift omitted
// (mathematically identical; logits are O(1) so exp cannot overflow)
__global__ void aggregate_kernel(const int* __restrict__ off, const int* __restrict__ csrc,
                                 const float* __restrict__ asrc, const float* __restrict__ adst,
                                 const float* __restrict__ ab,
                                 const __half* __restrict__ z,
                                 float* __restrict__ out, int n, int do_relu)
{
    int gw = (blockIdx.x * blockDim.x + threadIdx.x) >> 5;
    int ln = threadIdx.x & 31;
    if (gw >= n) return;
    const int beg = off[gw], end = off[gw + 1];
    const float dterm = adst[gw] + ab[0];

    float s = 0.f;
    float4 acc = make_float4(0.f, 0.f, 0.f, 0.f);
    int j = beg;
    for (; j + 2 <= end; j += 2) {
        int s0 = csrc[j];
        int s1 = csrc[j + 1];
        uint2 v0 = *(const uint2*)(z + (size_t)s0 * DIMF + ln * 4);
        uint2 v1 = *(const uint2*)(z + (size_t)s1 * DIMF + ln * 4);
        float e0 = asrc[s0] + dterm; e0 = e0 > 0.f ? e0 : 0.01f * e0;
        float e1 = asrc[s1] + dterm; e1 = e1 > 0.f ? e1 : 0.01f * e1;
        float w0 = __expf(e0);
        float w1 = __expf(e1);
        s += w0 + w1;
        float2 a0 = __half22float2(*(__half2*)&v0.x);
        float2 b0 = __half22float2(*(__half2*)&v0.y);
        float2 a1 = __half22float2(*(__half2*)&v1.x);
        float2 b1 = __half22float2(*(__half2*)&v1.y);
        acc.x += w0 * a0.x + w1 * a1.x;
        acc.y += w0 * a0.y + w1 * a1.y;
        acc.z += w0 * b0.x + w1 * b1.x;
        acc.w += w0 * b0.y + w1 * b1.y;
    }
    if (j < end) {
        int s0 = csrc[j];
        uint2 v0 = *(const uint2*)(z + (size_t)s0 * DIMF + ln * 4);
        float e0 = asrc[s0] + dterm; e0 = e0 > 0.f ? e0 : 0.01f * e0;
        float w0 = __expf(e0);
        s += w0;
        float2 a0 = __half22float2(*(__half2*)&v0.x);
        float2 b0 = __half22float2(*(__half2*)&v0.y);
        acc.x += w0 * a0.x;
        acc.y += w0 * a0.y;
        acc.z += w0 * b0.x;
        acc.w += w0 * b0.y;
    }
    const float sinv = (s > 0.f) ? (1.f / s) : 0.f;
    acc.x *= sinv; acc.y *= sinv; acc.z *= sinv; acc.w *= sinv;
    if (do_relu) {
        acc.x = fmaxf(acc.x, 0.f);
        acc.y = fmaxf(acc.y, 0.f);
        acc.z = fmaxf(acc.z, 0.f);
        acc.w = fmaxf(acc.w, 0.f);
    }
    *(float4*)(out + (size_t)gw * DIMF + ln * 4) = acc;
}

// ======================= host launcher =======================
extern "C" void kernel_launch(void* const* d_in, const int* in_sizes, int n_in,
                              void* d_out, int out_size)
{
    const float* x   = (const float*)d_in[0];
    const int*   src = (const int*)d_in[1];
    const int*   dst = (const int*)d_in[2];
    // d_in[3] = t (unused)
    const float* Wp[3]  = { (const float*)d_in[4],  (const float*)d_in[8],  (const float*)d_in[12] };
    const float* bp[3]  = { (const float*)d_in[5],  (const float*)d_in[9],  (const float*)d_in[13] };
    const float* aWp[3] = { (const float*)d_in[6],  (const float*)d_in[10], (const float*)d_in[14] };
    const float* abp[3] = { (const float*)d_in[7],  (const float*)d_in[11], (const float*)d_in[15] };

    const int n = in_sizes[0] / DIMF;
    const int e = in_sizes[1];
    if (n > NN_MAX || e > EE_MAX) return;

    __half* z;
    float *h, *as, *ad;
    int *deg, *off, *cur, *csrc;
    cudaGetSymbolAddress((void**)&z,    g_z);
    cudaGetSymbolAddress((void**)&h,    g_h);
    cudaGetSymbolAddress((void**)&as,   g_asrc);
    cudaGetSymbolAddress((void**)&ad,   g_adst);
    cudaGetSymbolAddress((void**)&deg,  g_deg);
    cudaGetSymbolAddress((void**)&off,  g_off);
    cudaGetSymbolAddress((void**)&cur,  g_cur);
    cudaGetSymbolAddress((void**)&csrc, g_csrc);

    const int smem_bytes = (DIMF * WT_STRIDE + BM * DIMF) * (int)sizeof(float);
    cudaFuncSetAttribute(gemm_attn_kernel,
                         cudaFuncAttributeMaxDynamicSharedMemorySize, smem_bytes);

    const int TB = 256;
    const int gb_e = (e + TB - 1) / TB;

    // ---- CSR build (shared by all 3 layers) ----
    cudaMemsetAsync(deg, 0, (size_t)n * sizeof(int));
    hist_kernel<<<gb_e, TB>>>(dst, deg, e);
    scan_kernel<<<1, 1024>>>(deg, off, cur, n);
    scatter_kernel<<<gb_e, TB>>>(src, dst, cur, csrc, e);

    const float* in = x;
    for (int l = 0; l < 3; l++) {
        gemm_attn_kernel<<<(n + BM - 1) / BM, 512, smem_bytes>>>(
            in, Wp[l], bp[l], aWp[l], z, as, ad, n);
        float* outp = (l == 2) ? (float*)d_out : h;
        aggregate_kernel<<<(n * 32 + TB - 1) / TB, TB>>>(
            off, csrc, as, ad, abp[l], z, outp, n, (l < 2) ? 1 : 0);
        in = h;
    }
}

// round 5
// speedup vs baseline: 1.6754x; 1.2625x over previous
#include <cuda_runtime.h>
#include <cuda_fp16.h>
#include <math.h>

#define NN_MAX 50000
#define EE_MAX 1600000
#define DIMF 128

// -------- scratch (static device globals; no allocation allowed) --------
__device__ __half g_z[NN_MAX * DIMF];
__device__ float  g_h[NN_MAX * DIMF];
__device__ float  g_asrc[NN_MAX];
__device__ float  g_adst[NN_MAX];
__device__ int    g_deg[NN_MAX];
__device__ int    g_off[NN_MAX + 1];
__device__ int    g_cur[NN_MAX];
__device__ int    g_csrc[EE_MAX];
__device__ float  g_wf[3 * 16384];   // W in tf32 fragment order, per layer

__device__ __forceinline__ float tf32r(float f) {
    unsigned u;
    asm("cvt.rna.tf32.f32 %0, %1;" : "=r"(u) : "f"(f));
    return __uint_as_float(u);
}

__device__ __forceinline__ void mma_tf32(float* d, const float4& a, const float2& b) {
    asm volatile(
        "mma.sync.aligned.m16n8k8.row.col.f32.tf32.tf32.f32 "
        "{%0,%1,%2,%3}, {%4,%5,%6,%7}, {%8,%9}, {%0,%1,%2,%3};"
        : "+f"(d[0]), "+f"(d[1]), "+f"(d[2]), "+f"(d[3])
        : "r"(__float_as_uint(a.x)), "r"(__float_as_uint(a.y)),
          "r"(__float_as_uint(a.z)), "r"(__float_as_uint(a.w)),
          "r"(__float_as_uint(b.x)), "r"(__float_as_uint(b.y)));
}

// ============ W repack: W[n][k] -> tf32 fragment order (once per layer) ============
// Bf layout: row r = (wn*16 + c)*4 + ni  (256 rows of 64 floats)
//            within row: lane*2 + reg ; b0=(k=c*8+tig, n=wn*32+ni*8+gid), b1=k+4
// One-time tiny kernel: reads straight from global (W is 64KB, L2-resident).
__global__ void wrepack_kernel(const float* __restrict__ W0,
                               const float* __restrict__ W1,
                               const float* __restrict__ W2,
                               float* __restrict__ wf)
{
    const float* W = (blockIdx.x == 0) ? W0 : (blockIdx.x == 1) ? W1 : W2;
    float* out = wf + blockIdx.x * 16384;
    const int tid = threadIdx.x;
#pragma unroll
    for (int j = 0; j < 32; j++) {
        int bf2 = tid + j * 256;           // float2 index, 8192 total
        int r = bf2 >> 5;
        int lane = bf2 & 31;
        int ni = r & 3, c = (r >> 2) & 15, wn = r >> 6;
        int gid = lane >> 2, tig = lane & 3;
        int nn = wn * 32 + ni * 8 + gid;
        int k0 = c * 8 + tig;
        float2 v;
        v.x = tf32r(W[nn * DIMF + k0]);
        v.y = tf32r(W[nn * DIMF + k0 + 4]);
        *(float2*)(out + bf2 * 2) = v;
    }
}

// ============ tensor-core GEMM + attention logits ============
// z[m][n] = sum_k x[m][k]*W[n][k] + b[n]  (z stored fp16)
// asrc[m] = z[m]·aW[0:128], adst[m] = z[m]·aW[128:256]
__global__ void __launch_bounds__(256, 1)
gemm_mma_kernel(const float* __restrict__ x,
                const float* __restrict__ Wf,
                const float* __restrict__ b,
                const float* __restrict__ aW,
                __half* __restrict__ z,
                float* __restrict__ asrc,
                float* __restrict__ adst,
                int n)
{
    extern __shared__ float sh[];
    float* xs  = sh;                     // [128][132] x tile (tf32-rounded)
    float* Af  = sh + 128 * 132;         // 16384 floats, fragment order
    float* sps = Af + 16384;             // [128] asrc partials
    float* spd = sps + 128;              // [128] adst partials
    const int tid = threadIdx.x;
    const int m0 = blockIdx.x * 128;

    if (tid < 128) { sps[tid] = 0.f; spd[tid] = 0.f; }

    // load x tile (coalesced float4), round to tf32
    for (int i = tid; i < 128 * 32; i += 256) {
        int mm = i >> 5;
        int k4 = (i & 31) * 4;
        int gm = m0 + mm;
        float4 v = make_float4(0.f, 0.f, 0.f, 0.f);
        if (gm < n) v = *(const float4*)(x + (size_t)gm * DIMF + k4);
        v.x = tf32r(v.x); v.y = tf32r(v.y); v.z = tf32r(v.z); v.w = tf32r(v.w);
        *(float4*)(xs + mm * 132 + k4) = v;
    }
    __syncthreads();

    // repack xs -> Af (fragment order). Scalar LDS with stride 132 spreads banks;
    // STS.128 contiguous.
#pragma unroll
    for (int i = 0; i < 16; i++) {
        int ft = tid + i * 256;            // float4 index, 4096 total
        int r = ft >> 5;                   // (wm*16 + c)*4 + mi
        int lane = ft & 31;
        int mi = r & 3, c = (r >> 2) & 15, wm = r >> 6;
        int gid = lane >> 2, tig = lane & 3;
        int r0 = wm * 64 + mi * 16 + gid;
        int k0 = c * 8 + tig;
        float4 v;
        v.x = xs[r0 * 132 + k0];           // a0 (gid,   tig)
        v.y = xs[(r0 + 8) * 132 + k0];     // a1 (gid+8, tig)
        v.z = xs[r0 * 132 + k0 + 4];       // a2 (gid,   tig+4)
        v.w = xs[(r0 + 8) * 132 + k0 + 4]; // a3 (gid+8, tig+4)
        *(float4*)(Af + ft * 4) = v;
    }
    __syncthreads();

    const int wid  = tid >> 5;
    const int lane = tid & 31;
    const int wm = wid >> 2;       // 0..1 (row half)
    const int wn = wid & 3;        // 0..3 (col quarter)

    float acc[4][4][4];
#pragma unroll
    for (int mi = 0; mi < 4; mi++)
#pragma unroll
        for (int ni = 0; ni < 4; ni++)
#pragma unroll
            for (int q = 0; q < 4; q++) acc[mi][ni][q] = 0.f;

    const float* AfW = Af + (wm * 16) * 4 * 128;
    const float* BfW = Wf + (wn * 16) * 4 * 64;

#pragma unroll
    for (int c = 0; c < 16; c++) {
        float4 a[4];
        float2 bb[4];
#pragma unroll
        for (int mi = 0; mi < 4; mi++)
            a[mi] = *(const float4*)(AfW + (c * 4 + mi) * 128 + lane * 4);
#pragma unroll
        for (int ni = 0; ni < 4; ni++)
            bb[ni] = *(const float2*)(BfW + (c * 4 + ni) * 64 + lane * 2);
#pragma unroll
        for (int mi = 0; mi < 4; mi++)
#pragma unroll
            for (int ni = 0; ni < 4; ni++)
                mma_tf32(acc[mi][ni], a[mi], bb[ni]);
    }

    // epilogue: bias, fp16 store, attention-logit partials
    const int gid = lane >> 2, tig = lane & 3;
#pragma unroll
    for (int mi = 0; mi < 4; mi++) {
        float ps0 = 0.f, pd0 = 0.f, ps1 = 0.f, pd1 = 0.f;
        int mloc0 = wm * 64 + mi * 16 + gid;
        int gm0 = m0 + mloc0;
        int gm1 = gm0 + 8;
#pragma unroll
        for (int ni = 0; ni < 4; ni++) {
            int ncol = wn * 32 + ni * 8 + 2 * tig;
            float bv0 = b[ncol], bv1 = b[ncol + 1];
            float c0 = acc[mi][ni][0] + bv0;
            float c1 = acc[mi][ni][1] + bv1;
            float c2 = acc[mi][ni][2] + bv0;
            float c3 = acc[mi][ni][3] + bv1;
            if (gm0 < n) {
                __half2 p = __floats2half2_rn(c0, c1);
                *(unsigned*)(z + (size_t)gm0 * DIMF + ncol) = *(unsigned*)&p;
            }
            if (gm1 < n) {
                __half2 p = __floats2half2_rn(c2, c3);
                *(unsigned*)(z + (size_t)gm1 * DIMF + ncol) = *(unsigned*)&p;
            }
            float al0 = aW[ncol], al1 = aW[ncol + 1];
            float ah0 = aW[DIMF + ncol], ah1 = aW[DIMF + ncol + 1];
            ps0 += c0 * al0 + c1 * al1;
            pd0 += c0 * ah0 + c1 * ah1;
            ps1 += c2 * al0 + c3 * al1;
            pd1 += c2 * ah0 + c3 * ah1;
        }
        // reduce across tig (4 consecutive lanes)
#pragma unroll
        for (int o = 1; o < 4; o <<= 1) {
            ps0 += __shfl_xor_sync(0xffffffffu, ps0, o);
            pd0 += __shfl_xor_sync(0xffffffffu, pd0, o);
            ps1 += __shfl_xor_sync(0xffffffffu, ps1, o);
            pd1 += __shfl_xor_sync(0xffffffffu, pd1, o);
        }
        if (tig == 0) {
            atomicAdd(&sps[mloc0], ps0);
            atomicAdd(&spd[mloc0], pd0);
            atomicAdd(&sps[mloc0 + 8], ps1);
            atomicAdd(&spd[mloc0 + 8], pd1);
        }
    }
    __syncthreads();
    if (tid < 128) {
        int gm = m0 + tid;
        if (gm < n) { asrc[gm] = sps[tid]; adst[gm] = spd[tid]; }
    }
}

// ======================= CSR build =======================
__global__ void hist_kernel(const int* __restrict__ dst, int* deg, int e) {
    int i = blockIdx.x * blockDim.x + threadIdx.x;
    if (i < e) atomicAdd(&deg[dst[i]], 1);
}

__global__ void scan_kernel(const int* __restrict__ deg, int* off, int* cur, int n) {
    __shared__ int wsum[32];
    __shared__ int carry;
    const int tid = threadIdx.x;
    const int lane = tid & 31;
    const int wid = tid >> 5;
    if (tid == 0) { carry = 0; off[0] = 0; }
    __syncthreads();
    for (int base = 0; base < n; base += 1024) {
        int idx = base + tid;
        int v = (idx < n) ? deg[idx] : 0;
        int x = v;
#pragma unroll
        for (int d = 1; d < 32; d <<= 1) {
            int t = __shfl_up_sync(0xffffffffu, x, d);
            if (lane >= d) x += t;
        }
        if (lane == 31) wsum[wid] = x;
        __syncthreads();
        if (wid == 0) {
            int y = wsum[lane];
#pragma unroll
            for (int d = 1; d < 32; d <<= 1) {
                int t = __shfl_up_sync(0xffffffffu, y, d);
                if (lane >= d) y += t;
            }
            wsum[lane] = y;
        }
        __syncthreads();
        int incl = x + (wid > 0 ? wsum[wid - 1] : 0) + carry;
        if (idx < n) { off[idx + 1] = incl; cur[idx] = incl - v; }
        __syncthreads();
        if (tid == 1023) carry = incl;
        __syncthreads();
    }
}

__global__ void scatter_kernel(const int* __restrict__ src, const int* __restrict__ dst,
                               int* cur, int* csrc, int e) {
    int i = blockIdx.x * blockDim.x + threadIdx.x;
    if (i < e) {
        int pos = atomicAdd(&cur[dst[i]], 1);
        csrc[pos] = src[i];
    }
}

// ========= fused softmax + aggregation, single pass: warp per dst node =========
__global__ void aggregate_kernel(const int* __restrict__ off, const int* __restrict__ csrc,
                                 const float* __restrict__ asrc, const float* __restrict__ adst,
                                 const float* __restrict__ ab,
                                 const __half* __restrict__ z,
                                 float* __restrict__ out, int n, int do_relu)
{
    int gw = (blockIdx.x * blockDim.x + threadIdx.x) >> 5;
    int ln = threadIdx.x & 31;
    if (gw >= n) return;
    const int beg = off[gw], end = off[gw + 1];
    const float dterm = adst[gw] + ab[0];

    float s = 0.f;
    float4 acc = make_float4(0.f, 0.f, 0.f, 0.f);
    int j = beg;
    for (; j + 2 <= end; j += 2) {
        int s0 = csrc[j];
        int s1 = csrc[j + 1];
        uint2 v0 = *(const uint2*)(z + (size_t)s0 * DIMF + ln * 4);
        uint2 v1 = *(const uint2*)(z + (size_t)s1 * DIMF + ln * 4);
        float e0 = asrc[s0] + dterm; e0 = e0 > 0.f ? e0 : 0.01f * e0;
        float e1 = asrc[s1] + dterm; e1 = e1 > 0.f ? e1 : 0.01f * e1;
        float w0 = __expf(e0);
        float w1 = __expf(e1);
        s += w0 + w1;
        float2 a0 = __half22float2(*(__half2*)&v0.x);
        float2 b0 = __half22float2(*(__half2*)&v0.y);
        float2 a1 = __half22float2(*(__half2*)&v1.x);
        float2 b1 = __half22float2(*(__half2*)&v1.y);
        acc.x += w0 * a0.x + w1 * a1.x;
        acc.y += w0 * a0.y + w1 * a1.y;
        acc.z += w0 * b0.x + w1 * b1.x;
        acc.w += w0 * b0.y + w1 * b1.y;
    }
    if (j < end) {
        int s0 = csrc[j];
        uint2 v0 = *(const uint2*)(z + (size_t)s0 * DIMF + ln * 4);
        float e0 = asrc[s0] + dterm; e0 = e0 > 0.f ? e0 : 0.01f * e0;
        float w0 = __expf(e0);
        s += w0;
        float2 a0 = __half22float2(*(__half2*)&v0.x);
        float2 b0 = __half22float2(*(__half2*)&v0.y);
        acc.x += w0 * a0.x;
        acc.y += w0 * a0.y;
        acc.z += w0 * b0.x;
        acc.w += w0 * b0.y;
    }
    const float sinv = (s > 0.f) ? (1.f / s) : 0.f;
    acc.x *= sinv; acc.y *= sinv; acc.z *= sinv; acc.w *= sinv;
    if (do_relu) {
        acc.x = fmaxf(acc.x, 0.f);
        acc.y = fmaxf(acc.y, 0.f);
        acc.z = fmaxf(acc.z, 0.f);
        acc.w = fmaxf(acc.w, 0.f);
    }
    *(float4*)(out + (size_t)gw * DIMF + ln * 4) = acc;
}

// ======================= host launcher =======================
extern "C" void kernel_launch(void* const* d_in, const int* in_sizes, int n_in,
                              void* d_out, int out_size)
{
    const float* x   = (const float*)d_in[0];
    const int*   src = (const int*)d_in[1];
    const int*   dst = (const int*)d_in[2];
    // d_in[3] = t (unused)
    const float* Wp[3]  = { (const float*)d_in[4],  (const float*)d_in[8],  (const float*)d_in[12] };
    const float* bp[3]  = { (const float*)d_in[5],  (const float*)d_in[9],  (const float*)d_in[13] };
    const float* aWp[3] = { (const float*)d_in[6],  (const float*)d_in[10], (const float*)d_in[14] };
    const float* abp[3] = { (const float*)d_in[7],  (const float*)d_in[11], (const float*)d_in[15] };

    const int n = in_sizes[0] / DIMF;
    const int e = in_sizes[1];
    if (n > NN_MAX || e > EE_MAX) return;

    __half* z;
    float *h, *as, *ad, *wf;
    int *deg, *off, *cur, *csrc;
    cudaGetSymbolAddress((void**)&z,    g_z);
    cudaGetSymbolAddress((void**)&h,    g_h);
    cudaGetSymbolAddress((void**)&as,   g_asrc);
    cudaGetSymbolAddress((void**)&ad,   g_adst);
    cudaGetSymbolAddress((void**)&deg,  g_deg);
    cudaGetSymbolAddress((void**)&off,  g_off);
    cudaGetSymbolAddress((void**)&cur,  g_cur);
    cudaGetSymbolAddress((void**)&csrc, g_csrc);
    cudaGetSymbolAddress((void**)&wf,   g_wf);

    const int gemm_smem = (128 * 132 + 16384 + 256) * (int)sizeof(float);
    cudaFuncSetAttribute(gemm_mma_kernel,
                         cudaFuncAttributeMaxDynamicSharedMemorySize, gemm_smem);

    const int TB = 256;
    const int gb_e = (e + TB - 1) / TB;

    // W repack for all 3 layers (independent of everything else)
    wrepack_kernel<<<3, 256>>>(Wp[0], Wp[1], Wp[2], wf);

    // ---- CSR build (shared by all 3 layers) ----
    cudaMemsetAsync(deg, 0, (size_t)n * sizeof(int));
    hist_kernel<<<gb_e, TB>>>(dst, deg, e);
    scan_kernel<<<1, 1024>>>(deg, off, cur, n);
    scatter_kernel<<<gb_e, TB>>>(src, dst, cur, csrc, e);

    const float* in = x;
    for (int l = 0; l < 3; l++) {
        gemm_mma_kernel<<<(n + 127) / 128, 256, gemm_smem>>>(
            in, wf + l * 16384, bp[l], aWp[l], z, as, ad, n);
        float* outp = (l == 2) ? (float*)d_out : h;
        aggregate_kernel<<<(n * 32 + TB - 1) / TB, TB>>>(
            off, csrc, as, ad, abp[l], z, outp, n, (l < 2) ? 1 : 0);
        in = h;
    }
}